// round 3
// baseline (speedup 1.0000x reference)
#include <cuda_runtime.h>

// Problem constants (from reference):
// B=16384, NUM_CARDS=64, NUM_WORDS=50, LEN_EMB=128, LEN_DENSE=128
#define NC 64
#define NW 50
#define D  128
#define EPS 1e-8f

__global__ __launch_bounds__(128, 8)
void imaginarium_kernel(const float* __restrict__ img,   // [B, NC, D]
                        const float* __restrict__ txt,   // [B, NW, D]
                        const float* __restrict__ y,     // [B, NC]
                        const float* __restrict__ W,     // [D, D] row-major (out, in)
                        const float* __restrict__ bias,  // [D]
                        float* __restrict__ out)         // [B, NW]
{
    const int b    = blockIdx.x;
    const int tid  = threadIdx.x;       // 128 threads
    const int lane = tid & 31;
    const int warp = tid >> 5;

    __shared__ float s_x[D];        // selected image row
    __shared__ float s_leader[D];   // Linear output
    __shared__ float s_logit[NW];
    __shared__ float s_red[4];
    __shared__ int   s_idx;

    // ---- 1) argmax over 64 cards (first-index tie-break, like jnp.argmax) ----
    if (warp == 0) {
        float v0 = y[(long)b * NC + lane];
        float v1 = y[(long)b * NC + lane + 32];
        float best; int bi;
        if (v1 > v0) { best = v1; bi = lane + 32; }  // tie -> keep lower index (v0)
        else         { best = v0; bi = lane; }
        #pragma unroll
        for (int off = 16; off; off >>= 1) {
            float ov = __shfl_down_sync(0xffffffffu, best, off);
            int   oi = __shfl_down_sync(0xffffffffu, bi,   off);
            if (ov > best || (ov == best && oi < bi)) { best = ov; bi = oi; }
        }
        if (lane == 0) s_idx = bi;
    }
    __syncthreads();
    const int idx = s_idx;

    // ---- 2) stage selected image row to smem ----
    s_x[tid] = img[((long)b * NC + idx) * D + tid];
    __syncthreads();

    // ---- 3) matvec: leader[e] = sum_d x[d] * W[e,d] + bias[e] ----
    // W row for this thread: 128 floats = 32 float4 (L1/L2-resident across grid)
    const float4* W4 = reinterpret_cast<const float4*>(W + (long)tid * D);
    float acc = 0.f;
    #pragma unroll
    for (int i = 0; i < 32; i++) {
        float4 w = __ldg(&W4[i]);
        acc += w.x * s_x[4*i+0] + w.y * s_x[4*i+1]
             + w.z * s_x[4*i+2] + w.w * s_x[4*i+3];
    }
    const float lv = acc + __ldg(&bias[tid]);
    s_leader[tid] = lv;

    // ---- 4) ||leader|| via block reduction ----
    float sq = lv * lv;
    #pragma unroll
    for (int off = 16; off; off >>= 1)
        sq += __shfl_down_sync(0xffffffffu, sq, off);
    if (lane == 0) s_red[warp] = sq;
    __syncthreads();
    const float na = sqrtf(s_red[0] + s_red[1] + s_red[2] + s_red[3]);

    // ---- 5) cosine similarity per word (float4-vectorized, warp per word) ----
    const float4* txt4 = reinterpret_cast<const float4*>(txt + (long)b * NW * D);
    const float4  l4   = reinterpret_cast<const float4*>(s_leader)[lane];
    for (int w = warp; w < NW; w += 4) {
        float4 t = txt4[w * 32 + lane];
        float dot = l4.x * t.x + l4.y * t.y + l4.z * t.z + l4.w * t.w;
        float nb2 = t.x * t.x + t.y * t.y + t.z * t.z + t.w * t.w;
        #pragma unroll
        for (int off = 16; off; off >>= 1) {
            dot += __shfl_down_sync(0xffffffffu, dot, off);
            nb2 += __shfl_down_sync(0xffffffffu, nb2, off);
        }
        if (lane == 0) {
            float nb = sqrtf(nb2);
            s_logit[w] = dot / fmaxf(na * nb, EPS);
        }
    }
    __syncthreads();

    // ---- 6) softmax over 50 words (single warp) ----
    if (warp == 0) {
        float v0 = s_logit[lane];                                    // lane < 32 < 50
        float v1 = (lane + 32 < NW) ? s_logit[lane + 32] : -1e30f;
        float m = fmaxf(v0, v1);
        #pragma unroll
        for (int off = 16; off; off >>= 1)
            m = fmaxf(m, __shfl_xor_sync(0xffffffffu, m, off));
        float e0 = __expf(v0 - m);
        float e1 = (lane + 32 < NW) ? __expf(v1 - m) : 0.f;
        float s = e0 + e1;
        #pragma unroll
        for (int off = 16; off; off >>= 1)
            s += __shfl_xor_sync(0xffffffffu, s, off);
        const float inv = 1.0f / s;
        float* o = out + (long)b * NW;
        o[lane] = e0 * inv;
        if (lane + 32 < NW) o[lane + 32] = e1 * inv;
    }
}

extern "C" void kernel_launch(void* const* d_in, const int* in_sizes, int n_in,
                              void* d_out, int out_size)
{
    const float* img  = (const float*)d_in[0];   // [B, 64, 128]
    const float* txt  = (const float*)d_in[1];   // [B, 50, 128]
    const float* yy   = (const float*)d_in[2];   // [B, 64]
    const float* W    = (const float*)d_in[3];   // [128, 128]
    const float* bias = (const float*)d_in[4];   // [128]
    float* out = (float*)d_out;                  // [B, 50]

    const int B = in_sizes[2] / NC;
    imaginarium_kernel<<<B, 128>>>(img, txt, yy, W, bias, out);
}

// round 6
// speedup vs baseline: 1.5814x; 1.5814x over previous
#include <cuda_runtime.h>

// B=16384, NUM_CARDS=64, NUM_WORDS=50, LEN_EMB=128, LEN_DENSE=128
#define NC 64
#define NW 50
#define D  128
#define TSTRIDE 132          // padded txt row stride in floats; conflict-free for LDS.128
#define EPS 1e-8f

__global__ __launch_bounds__(128, 8)
void imaginarium_kernel(const float* __restrict__ img,   // [B, NC, D]
                        const float* __restrict__ txt,   // [B, NW, D]
                        const float* __restrict__ y,     // [B, NC]
                        const float* __restrict__ W,     // [D, D] (out, in)
                        const float* __restrict__ bias,  // [D]
                        float* __restrict__ out)         // [B, NW]
{
    const int b    = blockIdx.x;
    const int tid  = threadIdx.x;       // 128 threads
    const int lane = tid & 31;
    const int warp = tid >> 5;

    __shared__ float s_txt[NW * TSTRIDE];   // 26.4 KB staged text tile
    __shared__ float s_x[D];                // selected image row
    __shared__ float s_leader[D];           // Linear output
    __shared__ float s_logit[NW];
    __shared__ float s_red[4];
    __shared__ int   s_idx;

    // ---- 0) kick off bulk txt staging via cp.async (deep MLP, overlapped) ----
    {
        const float4* g = reinterpret_cast<const float4*>(txt + (long)b * NW * D);
        unsigned s_base = (unsigned)__cvta_generic_to_shared(s_txt);
        // 1600 float4 total: 12 full sweeps of 128 threads + guarded tail of 64.
        #pragma unroll
        for (int k = 0; k < 12; k++) {
            int i = tid + k * 128;                 // 0..1535, unguarded
            int w = i >> 5, j = i & 31;
            unsigned saddr = s_base + (unsigned)(w * TSTRIDE + j * 4) * 4u;
            asm volatile("cp.async.ca.shared.global [%0], [%1], 16;\n"
                         :: "r"(saddr), "l"(g + i));
        }
        {
            int i = tid + 12 * 128;                // 1536..1663, guard at 1600
            if (i < NW * (D / 4)) {
                int w = i >> 5, j = i & 31;
                unsigned saddr = s_base + (unsigned)(w * TSTRIDE + j * 4) * 4u;
                asm volatile("cp.async.ca.shared.global [%0], [%1], 16;\n"
                             :: "r"(saddr), "l"(g + i));
            }
        }
        asm volatile("cp.async.commit_group;\n");
    }

    // ---- 1) argmax over 64 cards (first-index tie-break, like jnp.argmax) ----
    if (warp == 0) {
        float v0 = y[(long)b * NC + lane];
        float v1 = y[(long)b * NC + lane + 32];
        float best; int bi;
        if (v1 > v0) { best = v1; bi = lane + 32; }   // tie -> lower index (v0)
        else         { best = v0; bi = lane; }
        #pragma unroll
        for (int off = 16; off; off >>= 1) {
            float ov = __shfl_down_sync(0xffffffffu, best, off);
            int   oi = __shfl_down_sync(0xffffffffu, bi,   off);
            if (ov > best || (ov == best && oi < bi)) { best = ov; bi = oi; }
        }
        if (lane == 0) s_idx = bi;
    }
    __syncthreads();
    const int idx = s_idx;

    // ---- 2) gather selected image row ----
    s_x[tid] = img[((long)b * NC + idx) * D + tid];
    __syncthreads();

    // ---- 3) matvec: leader[e] = x · W[e,:] + bias[e]  (W is L1/L2-resident) ----
    const float4* W4 = reinterpret_cast<const float4*>(W + (long)tid * D);
    const float4* x4 = reinterpret_cast<const float4*>(s_x);
    float a0 = 0.f, a1 = 0.f;
    #pragma unroll
    for (int i = 0; i < 32; i += 2) {
        float4 w0 = __ldg(&W4[i]),   xv0 = x4[i];
        float4 w1 = __ldg(&W4[i+1]), xv1 = x4[i+1];
        a0 += w0.x*xv0.x + w0.y*xv0.y + w0.z*xv0.z + w0.w*xv0.w;
        a1 += w1.x*xv1.x + w1.y*xv1.y + w1.z*xv1.z + w1.w*xv1.w;
    }
    const float lv = a0 + a1 + __ldg(&bias[tid]);
    s_leader[tid] = lv;

    // ---- 4) ||leader||^2 partial reduction ----
    float sq = lv * lv;
    #pragma unroll
    for (int off = 16; off; off >>= 1)
        sq += __shfl_down_sync(0xffffffffu, sq, off);
    if (lane == 0) s_red[warp] = sq;

    // ---- 5) wait for txt tile; one barrier covers s_leader, s_red, s_txt ----
    asm volatile("cp.async.wait_group 0;\n" ::: "memory");
    __syncthreads();

    // ---- 6) cosine similarity: one thread per word, all operands in smem ----
    if (tid < NW) {
        const float na2 = s_red[0] + s_red[1] + s_red[2] + s_red[3];
        const float4* t4 = reinterpret_cast<const float4*>(s_txt + tid * TSTRIDE);
        const float4* l4 = reinterpret_cast<const float4*>(s_leader);
        float d0 = 0.f, d1 = 0.f, n0 = 0.f, n1 = 0.f;
        #pragma unroll
        for (int j = 0; j < 32; j += 2) {
            float4 t = t4[j],   l = l4[j];      // l4 reads are warp-broadcast
            float4 u = t4[j+1], m = l4[j+1];
            d0 += t.x*l.x + t.y*l.y + t.z*l.z + t.w*l.w;
            n0 += t.x*t.x + t.y*t.y + t.z*t.z + t.w*t.w;
            d1 += u.x*m.x + u.y*m.y + u.z*m.z + u.w*m.w;
            n1 += u.x*u.x + u.y*u.y + u.z*u.z + u.w*u.w;
        }
        float dot = d0 + d1;
        float nb2 = n0 + n1;
        s_logit[tid] = dot / fmaxf(sqrtf(na2) * sqrtf(nb2), EPS);
    }
    __syncthreads();

    // ---- 7) softmax over 50 words (single warp) ----
    if (warp == 0) {
        float v0 = s_logit[lane];
        float v1 = (lane + 32 < NW) ? s_logit[lane + 32] : -1e30f;
        float m = fmaxf(v0, v1);
        #pragma unroll
        for (int off = 16; off; off >>= 1)
            m = fmaxf(m, __shfl_xor_sync(0xffffffffu, m, off));
        float e0 = __expf(v0 - m);
        float e1 = (lane + 32 < NW) ? __expf(v1 - m) : 0.f;
        float s = e0 + e1;
        #pragma unroll
        for (int off = 16; off; off >>= 1)
            s += __shfl_xor_sync(0xffffffffu, s, off);
        const float inv = 1.0f / s;
        float* o = out + (long)b * NW;
        o[lane] = e0 * inv;
        if (lane + 32 < NW) o[lane + 32] = e1 * inv;
    }
}

extern "C" void kernel_launch(void* const* d_in, const int* in_sizes, int n_in,
                              void* d_out, int out_size)
{
    const float* img  = (const float*)d_in[0];   // [B, 64, 128]
    const float* txt  = (const float*)d_in[1];   // [B, 50, 128]
    const float* yy   = (const float*)d_in[2];   // [B, 64]
    const float* W    = (const float*)d_in[3];   // [128, 128]
    const float* bias = (const float*)d_in[4];   // [128]
    float* out = (float*)d_out;                  // [B, 50]

    // Unconditional (deterministic, idempotent, capture-safe host call):
    // maximize smem carveout so 8 CTAs/SM (26.6 KB each) fit.
    cudaFuncSetAttribute(imaginarium_kernel,
                         cudaFuncAttributePreferredSharedMemoryCarveout, 100);

    const int B = in_sizes[2] / NC;
    imaginarium_kernel<<<B, 128>>>(img, txt, yy, W, bias, out);
}

// round 10
// speedup vs baseline: 2.3837x; 1.5074x over previous
#include <cuda_runtime.h>

// B=16384, NUM_CARDS=64, NUM_WORDS=50, LEN_EMB=128, LEN_DENSE=128
#define NC 64
#define NW 50
#define D  128
#define NB 4                 // batch rows per CTA (amortizes W reads 4x)
#define EPS 1e-8f

__global__ __launch_bounds__(128, 8)
void imaginarium_kernel(const float* __restrict__ img,   // [B, NC, D]
                        const float* __restrict__ txt,   // [B, NW, D]
                        const float* __restrict__ y,     // [B, NC]
                        const float* __restrict__ W,     // [D, D] (out, in)
                        const float* __restrict__ bias,  // [D]
                        float* __restrict__ out)         // [B, NW]
{
    const int b0   = blockIdx.x * NB;
    const int tid  = threadIdx.x;       // 128 threads = 4 warps
    const int lane = tid & 31;
    const int warp = tid >> 5;          // warp nb owns batch b0+nb

    __shared__ float s_x[NB][D];        // selected image rows
    __shared__ float s_leader[NB][D];   // Linear outputs
    __shared__ float s_logit[NB][NW];
    __shared__ float s_red[4][NB];      // per-warp partial ||leader||^2
    __shared__ int   s_idx[NB];

    // ---- 1) argmax over 64 cards: warp nb handles batch b0+nb ----
    {
        const long yb = (long)(b0 + warp) * NC;
        float v0 = y[yb + lane];
        float v1 = y[yb + lane + 32];
        float best; int bi;
        if (v1 > v0) { best = v1; bi = lane + 32; }   // tie -> lower index
        else         { best = v0; bi = lane; }
        #pragma unroll
        for (int off = 16; off; off >>= 1) {
            float ov = __shfl_down_sync(0xffffffffu, best, off);
            int   oi = __shfl_down_sync(0xffffffffu, bi,   off);
            if (ov > best || (ov == best && oi < bi)) { best = ov; bi = oi; }
        }
        if (lane == 0) s_idx[warp] = bi;
    }
    __syncthreads();

    // ---- 2) gather NB selected image rows (all 128 threads cooperate) ----
    #pragma unroll
    for (int nb = 0; nb < NB; nb++)
        s_x[nb][tid] = img[((long)(b0 + nb) * NC + s_idx[nb]) * D + tid];
    __syncthreads();

    // ---- 3) matvec: each W float4 loaded ONCE, applied to 4 batches ----
    {
        const float4* W4 = reinterpret_cast<const float4*>(W + (long)tid * D);
        const float4* x0 = reinterpret_cast<const float4*>(s_x[0]);
        const float4* x1 = reinterpret_cast<const float4*>(s_x[1]);
        const float4* x2 = reinterpret_cast<const float4*>(s_x[2]);
        const float4* x3 = reinterpret_cast<const float4*>(s_x[3]);
        float a0 = 0.f, a1 = 0.f, a2 = 0.f, a3 = 0.f;
        #pragma unroll
        for (int i = 0; i < 32; i++) {
            float4 w = __ldg(&W4[i]);
            float4 v;
            v = x0[i]; a0 += w.x*v.x + w.y*v.y + w.z*v.z + w.w*v.w;   // LDS broadcast
            v = x1[i]; a1 += w.x*v.x + w.y*v.y + w.z*v.z + w.w*v.w;
            v = x2[i]; a2 += w.x*v.x + w.y*v.y + w.z*v.z + w.w*v.w;
            v = x3[i]; a3 += w.x*v.x + w.y*v.y + w.z*v.z + w.w*v.w;
        }
        const float bv = __ldg(&bias[tid]);
        const float l0 = a0 + bv, l1 = a1 + bv, l2 = a2 + bv, l3 = a3 + bv;
        s_leader[0][tid] = l0;  s_leader[1][tid] = l1;
        s_leader[2][tid] = l2;  s_leader[3][tid] = l3;

        // ---- 4) ||leader||^2 partials (per warp, all 4 batches) ----
        float q0 = l0*l0, q1 = l1*l1, q2 = l2*l2, q3 = l3*l3;
        #pragma unroll
        for (int off = 16; off; off >>= 1) {
            q0 += __shfl_down_sync(0xffffffffu, q0, off);
            q1 += __shfl_down_sync(0xffffffffu, q1, off);
            q2 += __shfl_down_sync(0xffffffffu, q2, off);
            q3 += __shfl_down_sync(0xffffffffu, q3, off);
        }
        if (lane == 0) {
            s_red[warp][0] = q0; s_red[warp][1] = q1;
            s_red[warp][2] = q2; s_red[warp][3] = q3;
        }
    }
    __syncthreads();

    // ---- 5) cosine similarity: warp nb streams its batch's txt from global ----
    {
        const int  bb = b0 + warp;
        const float4* t4 = reinterpret_cast<const float4*>(txt + (long)bb * NW * D);
        const float4  l4 = reinterpret_cast<const float4*>(s_leader[warp])[lane];
        const float na = sqrtf(s_red[0][warp] + s_red[1][warp] +
                               s_red[2][warp] + s_red[3][warp]);
        const float rna = 1.0f / fmaxf(na, 1e-20f);   // na>0 a.s.; guard anyway
        #pragma unroll
        for (int g = 0; g < 10; g++) {                // 5 words in flight, MLP=5
            const float4* p = t4 + (5 * g) * 32 + lane;
            float4 t0 = __ldcs(p);                    // read-once: stream past L2
            float4 t1 = __ldcs(p + 32);
            float4 t2 = __ldcs(p + 64);
            float4 t3 = __ldcs(p + 96);
            float4 tv = __ldcs(p + 128);
            float d0 = t0.x*l4.x + t0.y*l4.y + t0.z*l4.z + t0.w*l4.w;
            float n0 = t0.x*t0.x + t0.y*t0.y + t0.z*t0.z + t0.w*t0.w;
            float d1 = t1.x*l4.x + t1.y*l4.y + t1.z*l4.z + t1.w*l4.w;
            float n1 = t1.x*t1.x + t1.y*t1.y + t1.z*t1.z + t1.w*t1.w;
            float d2 = t2.x*l4.x + t2.y*l4.y + t2.z*l4.z + t2.w*l4.w;
            float n2 = t2.x*t2.x + t2.y*t2.y + t2.z*t2.z + t2.w*t2.w;
            float d3 = t3.x*l4.x + t3.y*l4.y + t3.z*l4.z + t3.w*l4.w;
            float n3 = t3.x*t3.x + t3.y*t3.y + t3.z*t3.z + t3.w*t3.w;
            float d4 = tv.x*l4.x + tv.y*l4.y + tv.z*l4.z + tv.w*l4.w;
            float n4 = tv.x*tv.x + tv.y*tv.y + tv.z*tv.z + tv.w*tv.w;
            #pragma unroll
            for (int off = 16; off; off >>= 1) {
                d0 += __shfl_down_sync(0xffffffffu, d0, off);
                n0 += __shfl_down_sync(0xffffffffu, n0, off);
                d1 += __shfl_down_sync(0xffffffffu, d1, off);
                n1 += __shfl_down_sync(0xffffffffu, n1, off);
                d2 += __shfl_down_sync(0xffffffffu, d2, off);
                n2 += __shfl_down_sync(0xffffffffu, n2, off);
                d3 += __shfl_down_sync(0xffffffffu, d3, off);
                n3 += __shfl_down_sync(0xffffffffu, n3, off);
                d4 += __shfl_down_sync(0xffffffffu, d4, off);
                n4 += __shfl_down_sync(0xffffffffu, n4, off);
            }
            if (lane == 0) {
                s_logit[warp][5*g+0] = d0 * rna / fmaxf(sqrtf(n0), EPS * rna * na);
                s_logit[warp][5*g+1] = d1 * rna / fmaxf(sqrtf(n1), EPS * rna * na);
                s_logit[warp][5*g+2] = d2 * rna / fmaxf(sqrtf(n2), EPS * rna * na);
                s_logit[warp][5*g+3] = d3 * rna / fmaxf(sqrtf(n3), EPS * rna * na);
                s_logit[warp][5*g+4] = d4 * rna / fmaxf(sqrtf(n4), EPS * rna * na);
            }
        }
        __syncwarp();

        // ---- 6) softmax over 50 words (per warp, own batch) ----
        float v0 = s_logit[warp][lane];
        float v1 = (lane + 32 < NW) ? s_logit[warp][lane + 32] : -1e30f;
        float m = fmaxf(v0, v1);
        #pragma unroll
        for (int off = 16; off; off >>= 1)
            m = fmaxf(m, __shfl_xor_sync(0xffffffffu, m, off));
        float e0 = __expf(v0 - m);
        float e1 = (lane + 32 < NW) ? __expf(v1 - m) : 0.f;
        float s = e0 + e1;
        #pragma unroll
        for (int off = 16; off; off >>= 1)
            s += __shfl_xor_sync(0xffffffffu, s, off);
        const float inv = 1.0f / s;
        float* o = out + (long)bb * NW;
        o[lane] = e0 * inv;
        if (lane + 32 < NW) o[lane + 32] = e1 * inv;
    }
}

extern "C" void kernel_launch(void* const* d_in, const int* in_sizes, int n_in,
                              void* d_out, int out_size)
{
    const float* img  = (const float*)d_in[0];   // [B, 64, 128]
    const float* txt  = (const float*)d_in[1];   // [B, 50, 128]
    const float* yy   = (const float*)d_in[2];   // [B, 64]
    const float* W    = (const float*)d_in[3];   // [128, 128]
    const float* bias = (const float*)d_in[4];   // [128]
    float* out = (float*)d_out;                  // [B, 50]

    const int B = in_sizes[2] / NC;              // 16384, divisible by NB
    imaginarium_kernel<<<B / NB, 128>>>(img, txt, yy, W, bias, out);
}

// round 11
// speedup vs baseline: 4.2965x; 1.8024x over previous
#include <cuda_runtime.h>

// B=16384, NUM_CARDS=64, NUM_WORDS=50, LEN_EMB=128, LEN_DENSE=128
#define NC 64
#define NW 50
#define D  128
#define NB 4                 // batch rows per CTA (amortizes W reads 4x)
#define EPS 1e-8f

__global__ __launch_bounds__(128, 8)
void imaginarium_kernel(const float* __restrict__ img,   // [B, NC, D]
                        const float* __restrict__ txt,   // [B, NW, D]
                        const float* __restrict__ y,     // [B, NC]
                        const float* __restrict__ W,     // [D, D] (out, in)
                        const float* __restrict__ bias,  // [D]
                        float* __restrict__ out)         // [B, NW]
{
    const int b0   = blockIdx.x * NB;
    const int tid  = threadIdx.x;       // 128 threads = 4 warps
    const int lane = tid & 31;
    const int warp = tid >> 5;          // warp nb owns batch b0+nb

    __shared__ float s_x[NB][D];        // selected image rows
    __shared__ float s_leader[NB][D];   // Linear outputs
    __shared__ float s_logit[NB][NW];
    __shared__ float s_red[4][NB];      // per-warp partial ||leader||^2
    __shared__ int   s_idx[NB];

    // ---- 1) argmax over 64 cards: warp nb handles batch b0+nb ----
    {
        const long yb = (long)(b0 + warp) * NC;
        float v0 = y[yb + lane];
        float v1 = y[yb + lane + 32];
        float best; int bi;
        if (v1 > v0) { best = v1; bi = lane + 32; }   // tie -> lower index
        else         { best = v0; bi = lane; }
        #pragma unroll
        for (int off = 16; off; off >>= 1) {
            float ov = __shfl_down_sync(0xffffffffu, best, off);
            int   oi = __shfl_down_sync(0xffffffffu, bi,   off);
            if (ov > best || (ov == best && oi < bi)) { best = ov; bi = oi; }
        }
        if (lane == 0) s_idx[warp] = bi;
    }
    __syncthreads();

    // ---- 2) gather NB selected image rows (all 128 threads cooperate) ----
    #pragma unroll
    for (int nb = 0; nb < NB; nb++)
        s_x[nb][tid] = img[((long)(b0 + nb) * NC + s_idx[nb]) * D + tid];
    __syncthreads();

    // ---- 3) matvec: each W float4 loaded ONCE, applied to 4 batches ----
    {
        const float4* W4 = reinterpret_cast<const float4*>(W + (long)tid * D);
        const float4* x0 = reinterpret_cast<const float4*>(s_x[0]);
        const float4* x1 = reinterpret_cast<const float4*>(s_x[1]);
        const float4* x2 = reinterpret_cast<const float4*>(s_x[2]);
        const float4* x3 = reinterpret_cast<const float4*>(s_x[3]);
        float a0 = 0.f, a1 = 0.f, a2 = 0.f, a3 = 0.f;
        #pragma unroll
        for (int i = 0; i < 32; i++) {
            float4 w = __ldg(&W4[i]);
            float4 v;
            v = x0[i]; a0 += w.x*v.x + w.y*v.y + w.z*v.z + w.w*v.w;   // LDS broadcast
            v = x1[i]; a1 += w.x*v.x + w.y*v.y + w.z*v.z + w.w*v.w;
            v = x2[i]; a2 += w.x*v.x + w.y*v.y + w.z*v.z + w.w*v.w;
            v = x3[i]; a3 += w.x*v.x + w.y*v.y + w.z*v.z + w.w*v.w;
        }
        const float bv = __ldg(&bias[tid]);
        const float l0 = a0 + bv, l1 = a1 + bv, l2 = a2 + bv, l3 = a3 + bv;
        s_leader[0][tid] = l0;  s_leader[1][tid] = l1;
        s_leader[2][tid] = l2;  s_leader[3][tid] = l3;

        // ---- 4) ||leader||^2 partials (per warp, all 4 batches) ----
        float q0 = l0*l0, q1 = l1*l1, q2 = l2*l2, q3 = l3*l3;
        #pragma unroll
        for (int off = 16; off; off >>= 1) {
            q0 += __shfl_down_sync(0xffffffffu, q0, off);
            q1 += __shfl_down_sync(0xffffffffu, q1, off);
            q2 += __shfl_down_sync(0xffffffffu, q2, off);
            q3 += __shfl_down_sync(0xffffffffu, q3, off);
        }
        if (lane == 0) {
            s_red[warp][0] = q0; s_red[warp][1] = q1;
            s_red[warp][2] = q2; s_red[warp][3] = q3;
        }
    }
    __syncthreads();

    // ---- 5) cosine similarity: 8 lanes per word, 4 words per warp-step ----
    {
        const int  bb  = b0 + warp;
        const int  sub = lane >> 3;     // word slot within group of 4
        const int  sl  = lane & 7;      // position within word (8 lanes * float4 * 4 = 128)
        const float4* t4 = reinterpret_cast<const float4*>(txt + (long)bb * NW * D);
        const float4* ld4 = reinterpret_cast<const float4*>(s_leader[warp]);
        // leader float4s this lane needs (same for every word); 8 distinct
        // addresses per instr -> 1 wavefront each, read once per batch
        const float4 L0 = ld4[sl], L1 = ld4[sl + 8], L2 = ld4[sl + 16], L3 = ld4[sl + 24];
        const float na = sqrtf(s_red[0][warp] + s_red[1][warp] +
                               s_red[2][warp] + s_red[3][warp]);

        #pragma unroll
        for (int wi = 0; wi < 13; wi++) {           // 13*4 = 52 slots, 2 masked
            const int word  = wi * 4 + sub;
            const int aw    = word < NW ? word : NW - 1;   // clamp reads, mask store
            const float4* p = t4 + aw * 32 + sl;
            float4 a = __ldcs(p);                   // 4 contiguous 128B lines/instr
            float4 b = __ldcs(p + 8);
            float4 c = __ldcs(p + 16);
            float4 e = __ldcs(p + 24);
            float d = a.x*L0.x + a.y*L0.y + a.z*L0.z + a.w*L0.w
                    + b.x*L1.x + b.y*L1.y + b.z*L1.z + b.w*L1.w
                    + c.x*L2.x + c.y*L2.y + c.z*L2.z + c.w*L2.w
                    + e.x*L3.x + e.y*L3.y + e.z*L3.z + e.w*L3.w;
            float n = a.x*a.x + a.y*a.y + a.z*a.z + a.w*a.w
                    + b.x*b.x + b.y*b.y + b.z*b.z + b.w*b.w
                    + c.x*c.x + c.y*c.y + c.z*c.z + c.w*c.w
                    + e.x*e.x + e.y*e.y + e.z*e.z + e.w*e.w;
            // reduce across the 8-lane group: 3 rounds, 4 words at once
            #pragma unroll
            for (int off = 4; off; off >>= 1) {
                d += __shfl_down_sync(0xffffffffu, d, off, 8);
                n += __shfl_down_sync(0xffffffffu, n, off, 8);
            }
            if (sl == 0 && word < NW)
                s_logit[warp][word] = d / fmaxf(na * sqrtf(n), EPS);
        }
        __syncwarp();

        // ---- 6) softmax over 50 words (per warp, own batch) ----
        float v0 = s_logit[warp][lane];
        float v1 = (lane + 32 < NW) ? s_logit[warp][lane + 32] : -1e30f;
        float m = fmaxf(v0, v1);
        #pragma unroll
        for (int off = 16; off; off >>= 1)
            m = fmaxf(m, __shfl_xor_sync(0xffffffffu, m, off));
        float e0 = __expf(v0 - m);
        float e1 = (lane + 32 < NW) ? __expf(v1 - m) : 0.f;
        float s = e0 + e1;
        #pragma unroll
        for (int off = 16; off; off >>= 1)
            s += __shfl_xor_sync(0xffffffffu, s, off);
        const float inv = 1.0f / s;
        float* o = out + (long)bb * NW;
        o[lane] = e0 * inv;
        if (lane + 32 < NW) o[lane + 32] = e1 * inv;
    }
}

extern "C" void kernel_launch(void* const* d_in, const int* in_sizes, int n_in,
                              void* d_out, int out_size)
{
    const float* img  = (const float*)d_in[0];   // [B, 64, 128]
    const float* txt  = (const float*)d_in[1];   // [B, 50, 128]
    const float* yy   = (const float*)d_in[2];   // [B, 64]
    const float* W    = (const float*)d_in[3];   // [128, 128]
    const float* bias = (const float*)d_in[4];   // [128]
    float* out = (float*)d_out;                  // [B, 50]

    const int B = in_sizes[2] / NC;              // 16384, divisible by NB
    imaginarium_kernel<<<B / NB, 128>>>(img, txt, yy, W, bias, out);
}

// round 12
// speedup vs baseline: 5.6470x; 1.3143x over previous
#include <cuda_runtime.h>

// B=16384, NUM_CARDS=64, NUM_WORDS=50, LEN_EMB=128, LEN_DENSE=128
#define NC 64
#define NW 50
#define D  128
#define NB 4                 // batch rows per CTA
#define EPS 1e-8f

// Transposed, float4-of-d packed W: WT[k][e] = float4(W[e][4k..4k+4)), k<32, e<128.
// 64 KB static scratch (allocation-free), rewritten every launch (deterministic).
__device__ float4 g_WT[32 * 128];

__global__ void transpose_W_kernel(const float* __restrict__ W)
{
    const int j = blockIdx.x * blockDim.x + threadIdx.x;   // 0..4095
    const int k = j >> 7;          // d-chunk
    const int e = j & 127;         // output index
    g_WT[j] = reinterpret_cast<const float4*>(W)[e * 32 + k];
}

__global__ __launch_bounds__(128, 8)
void imaginarium_kernel(const float* __restrict__ img,   // [B, NC, D]
                        const float* __restrict__ txt,   // [B, NW, D]
                        const float* __restrict__ y,     // [B, NC]
                        const float* __restrict__ bias,  // [D]
                        float* __restrict__ out)         // [B, NW]
{
    const int b0   = blockIdx.x * NB;
    const int tid  = threadIdx.x;       // 128 threads = 4 warps
    const int lane = tid & 31;
    const int warp = tid >> 5;          // warp nb owns batch b0+nb

    __shared__ float s_x[NB][D];        // selected image rows
    __shared__ float s_leader[NB][D];   // Linear outputs
    __shared__ float s_logit[NB][NW];
    __shared__ float s_red[4][NB];      // per-warp partial ||leader||^2
    __shared__ int   s_idx[NB];

    // ---- 1) argmax over 64 cards: warp nb handles batch b0+nb ----
    {
        const long yb = (long)(b0 + warp) * NC;
        float v0 = y[yb + lane];
        float v1 = y[yb + lane + 32];
        float best; int bi;
        if (v1 > v0) { best = v1; bi = lane + 32; }   // tie -> lower index
        else         { best = v0; bi = lane; }
        #pragma unroll
        for (int off = 16; off; off >>= 1) {
            float ov = __shfl_down_sync(0xffffffffu, best, off);
            int   oi = __shfl_down_sync(0xffffffffu, bi,   off);
            if (ov > best || (ov == best && oi < bi)) { best = ov; bi = oi; }
        }
        if (lane == 0) s_idx[warp] = bi;
    }
    __syncthreads();

    // ---- 2) gather NB selected image rows (all 128 threads cooperate) ----
    #pragma unroll
    for (int nb = 0; nb < NB; nb++)
        s_x[nb][tid] = img[((long)(b0 + nb) * NC + s_idx[nb]) * D + tid];
    __syncthreads();

    // ---- 3) matvec with COALESCED transposed W: thread owns e=tid ----
    // Per k: one LDG.128 across the CTA (128 consecutive float4) = fully-used
    // wavefronts; x chunks are LDS broadcasts. No cross-lane reductions.
    {
        const float4* x0 = reinterpret_cast<const float4*>(s_x[0]);
        const float4* x1 = reinterpret_cast<const float4*>(s_x[1]);
        const float4* x2 = reinterpret_cast<const float4*>(s_x[2]);
        const float4* x3 = reinterpret_cast<const float4*>(s_x[3]);
        float a0 = 0.f, a1 = 0.f, a2 = 0.f, a3 = 0.f;
        #pragma unroll
        for (int k = 0; k < 32; k++) {
            const float4 w = g_WT[k * 128 + tid];   // coalesced, L1/L2-resident
            float4 v;
            v = x0[k]; a0 += w.x*v.x + w.y*v.y + w.z*v.z + w.w*v.w;
            v = x1[k]; a1 += w.x*v.x + w.y*v.y + w.z*v.z + w.w*v.w;
            v = x2[k]; a2 += w.x*v.x + w.y*v.y + w.z*v.z + w.w*v.w;
            v = x3[k]; a3 += w.x*v.x + w.y*v.y + w.z*v.z + w.w*v.w;
        }
        const float bv = __ldg(&bias[tid]);
        const float l0 = a0 + bv, l1 = a1 + bv, l2 = a2 + bv, l3 = a3 + bv;
        s_leader[0][tid] = l0;  s_leader[1][tid] = l1;
        s_leader[2][tid] = l2;  s_leader[3][tid] = l3;

        // ---- 4) ||leader||^2 partials (per warp, all 4 batches) ----
        float q0 = l0*l0, q1 = l1*l1, q2 = l2*l2, q3 = l3*l3;
        #pragma unroll
        for (int off = 16; off; off >>= 1) {
            q0 += __shfl_down_sync(0xffffffffu, q0, off);
            q1 += __shfl_down_sync(0xffffffffu, q1, off);
            q2 += __shfl_down_sync(0xffffffffu, q2, off);
            q3 += __shfl_down_sync(0xffffffffu, q3, off);
        }
        if (lane == 0) {
            s_red[warp][0] = q0; s_red[warp][1] = q1;
            s_red[warp][2] = q2; s_red[warp][3] = q3;
        }
    }
    __syncthreads();

    // ---- 5) cosine similarity: 8 lanes per word, 4 words per warp-step ----
    {
        const int  bb  = b0 + warp;
        const int  sub = lane >> 3;     // word slot within group of 4
        const int  sl  = lane & 7;      // position within word
        const float4* t4  = reinterpret_cast<const float4*>(txt + (long)bb * NW * D);
        const float4* ld4 = reinterpret_cast<const float4*>(s_leader[warp]);
        const float4 L0 = ld4[sl], L1 = ld4[sl + 8], L2 = ld4[sl + 16], L3 = ld4[sl + 24];
        const float na = sqrtf(s_red[0][warp] + s_red[1][warp] +
                               s_red[2][warp] + s_red[3][warp]);

        #pragma unroll
        for (int wi = 0; wi < 13; wi++) {           // 13*4 = 52 slots, 2 masked
            const int word  = wi * 4 + sub;
            const int aw    = word < NW ? word : NW - 1;   // clamp reads, mask store
            const float4* p = t4 + aw * 32 + sl;
            float4 a = __ldcs(p);                   // 4 contiguous 128B lines/instr
            float4 b = __ldcs(p + 8);
            float4 c = __ldcs(p + 16);
            float4 e = __ldcs(p + 24);
            float d = a.x*L0.x + a.y*L0.y + a.z*L0.z + a.w*L0.w
                    + b.x*L1.x + b.y*L1.y + b.z*L1.z + b.w*L1.w
                    + c.x*L2.x + c.y*L2.y + c.z*L2.z + c.w*L2.w
                    + e.x*L3.x + e.y*L3.y + e.z*L3.z + e.w*L3.w;
            float n = a.x*a.x + a.y*a.y + a.z*a.z + a.w*a.w
                    + b.x*b.x + b.y*b.y + b.z*b.z + b.w*b.w
                    + c.x*c.x + c.y*c.y + c.z*c.z + c.w*c.w
                    + e.x*e.x + e.y*e.y + e.z*e.z + e.w*e.w;
            #pragma unroll
            for (int off = 4; off; off >>= 1) {     // 3 rounds over 8 lanes
                d += __shfl_down_sync(0xffffffffu, d, off, 8);
                n += __shfl_down_sync(0xffffffffu, n, off, 8);
            }
            if (sl == 0 && word < NW)
                s_logit[warp][word] = d / fmaxf(na * sqrtf(n), EPS);
        }
        __syncwarp();

        // ---- 6) softmax over 50 words (per warp, own batch) ----
        float v0 = s_logit[warp][lane];
        float v1 = (lane + 32 < NW) ? s_logit[warp][lane + 32] : -1e30f;
        float m = fmaxf(v0, v1);
        #pragma unroll
        for (int off = 16; off; off >>= 1)
            m = fmaxf(m, __shfl_xor_sync(0xffffffffu, m, off));
        float e0 = __expf(v0 - m);
        float e1 = (lane + 32 < NW) ? __expf(v1 - m) : 0.f;
        float s = e0 + e1;
        #pragma unroll
        for (int off = 16; off; off >>= 1)
            s += __shfl_xor_sync(0xffffffffu, s, off);
        const float inv = 1.0f / s;
        float* o = out + (long)bb * NW;
        o[lane] = e0 * inv;
        if (lane + 32 < NW) o[lane + 32] = e1 * inv;
    }
}

extern "C" void kernel_launch(void* const* d_in, const int* in_sizes, int n_in,
                              void* d_out, int out_size)
{
    const float* img  = (const float*)d_in[0];   // [B, 64, 128]
    const float* txt  = (const float*)d_in[1];   // [B, 50, 128]
    const float* yy   = (const float*)d_in[2];   // [B, 64]
    const float* W    = (const float*)d_in[3];   // [128, 128]
    const float* bias = (const float*)d_in[4];   // [128]
    float* out = (float*)d_out;                  // [B, 50]

    const int B = in_sizes[2] / NC;              // 16384, divisible by NB

    // Prologue: pack W into transposed float4-of-d layout (same stream ->
    // ordered before the main kernel; both launches are capture-safe).
    transpose_W_kernel<<<16, 256>>>(W);
    imaginarium_kernel<<<B / NB, 128>>>(img, txt, yy, bias, out);
}